// round 7
// baseline (speedup 1.0000x reference)
#include <cuda_runtime.h>

#define POOL 14
#define H 128
#define W 128
#define C 1024
#define R 256
#define C4 (C / 4)

// R6 kernel (best: 53.3us) with exactly ONE change: __launch_bounds__(256,6)
// caps regs at 40 -> 6 CTAs/SM (75% theoretical occupancy, was 5/62.5%).
// Inner loop untouched: full 14-px unroll, 4 straight LDG.128 + lerp +
// streaming STG.128; zero-weight corners aliased to the loaded address in
// the precompute (L1 hits, bit-exact).
__global__ __launch_bounds__(256, 6) void roi_resize_kernel(
    const float4* __restrict__ img,   // [H, W, C4]
    const float*  __restrict__ rois,  // [R, 4]
    float4*       __restrict__ out)   // [R, POOL, POOL, C4]
{
    const int py = blockIdx.x;          // 0..13
    const int r  = blockIdx.y;          // 0..255
    const int c4 = threadIdx.x;         // 0..255

    __shared__ int   s_ax0[POOL];
    __shared__ int   s_ax1[POOL];
    __shared__ float s_fx [POOL];

    const int x1 = (int)rois[r * 4 + 0];
    const int y1 = (int)rois[r * 4 + 1];
    const int x2 = (int)rois[r * 4 + 2];
    const int y2 = (int)rois[r * 4 + 3];

    if (threadIdx.x < POOL) {
        const float ww = (float)(x2 - x1);
        const float src_x = (float)threadIdx.x * (ww * (1.0f / POOL));
        const int   x0 = (int)floorf(src_x);
        const int   x1i = min(x0 + 1, (x2 - x1) - 1);
        const float fx = src_x - (float)x0;
        const int   ax0 = min(max(x1 + x0, 0), W - 1);
        int         ax1 = min(max(x1 + x1i, 0), W - 1);
        if (fx == 0.0f) ax1 = ax0;      // zero-weight corner -> alias address
        s_fx [threadIdx.x] = fx;
        s_ax0[threadIdx.x] = ax0;
        s_ax1[threadIdx.x] = ax1;
    }

    const float hh = (float)(y2 - y1);
    const float src_y = (float)py * (hh * (1.0f / POOL));
    const int   y0 = (int)floorf(src_y);
    const float fy = src_y - (float)y0;
    const int   y1i = min(y0 + 1, (y2 - y1) - 1);
    const int   ay0 = min(max(y1 + y0, 0), H - 1);
    int         ay1 = min(max(y1 + y1i, 0), H - 1);
    if (fy == 0.0f) ay1 = ay0;          // zero-weight row -> alias address

    __syncthreads();

    const float4* __restrict__ row0 = img + (size_t)(ay0 * W) * C4 + c4;
    const float4* __restrict__ row1 = img + (size_t)(ay1 * W) * C4 + c4;
    float4* __restrict__ orow = out + ((size_t)(r * POOL + py) * POOL) * C4 + c4;

    #pragma unroll
    for (int px = 0; px < POOL; px++) {
        const int   ax0 = s_ax0[px];
        const int   ax1 = s_ax1[px];
        const float fx  = s_fx[px];

        const float4 v00 = row0[ax0 * C4];
        const float4 v01 = row0[ax1 * C4];
        const float4 v10 = row1[ax0 * C4];
        const float4 v11 = row1[ax1 * C4];

        float4 o;
        {
            float top = v00.x + (v01.x - v00.x) * fx;
            float bot = v10.x + (v11.x - v10.x) * fx;
            o.x = top + (bot - top) * fy;
        }
        {
            float top = v00.y + (v01.y - v00.y) * fx;
            float bot = v10.y + (v11.y - v10.y) * fx;
            o.y = top + (bot - top) * fy;
        }
        {
            float top = v00.z + (v01.z - v00.z) * fx;
            float bot = v10.z + (v11.z - v10.z) * fx;
            o.z = top + (bot - top) * fy;
        }
        {
            float top = v00.w + (v01.w - v00.w) * fx;
            float bot = v10.w + (v11.w - v10.w) * fx;
            o.w = top + (bot - top) * fy;
        }

        __stcs(&orow[(size_t)px * C4], o);
    }
}

extern "C" void kernel_launch(void* const* d_in, const int* in_sizes, int n_in,
                              void* d_out, int out_size) {
    const float4* img  = (const float4*)d_in[0];
    const float*  rois = (const float*)d_in[1];
    float4*       out  = (float4*)d_out;

    dim3 grid(POOL, R);
    roi_resize_kernel<<<grid, 256>>>(img, rois, out);
}

// round 8
// speedup vs baseline: 1.5072x; 1.5072x over previous
#include <cuda_runtime.h>

#define POOL 14
#define H 128
#define W 128
#define C 1024
#define R 256
#define C4 (C / 4)

// R6 kernel (best: 53.3us) with exactly ONE change: __stcs -> __stwt.
// Output is write-once never-read; write-through bypasses L2 allocation so
// ~205MB of store data no longer transits the L2 arrays (img stays fully
// resident, L2 pipe load drops). Kernel is otherwise at the DRAM write-
// bandwidth ceiling (~4.0TB/s of pure writes measured).
//
// Structure: one CTA per (roi, py) row, 256 threads = one float4 channel-
// group each, x-side tuples in shared, full 14-px unroll, 4 straight
// LDG.128 + lerp per px. Zero-weight corners aliased to the already-loaded
// address in the precompute (bit-exact, converts them to L1 hits).
// NO launch_bounds minimum: ptxas needs 48 regs to batch the loads (the
// 40-reg cap cost +68% in R7).
__global__ __launch_bounds__(256) void roi_resize_kernel(
    const float4* __restrict__ img,   // [H, W, C4]
    const float*  __restrict__ rois,  // [R, 4]
    float4*       __restrict__ out)   // [R, POOL, POOL, C4]
{
    const int py = blockIdx.x;          // 0..13
    const int r  = blockIdx.y;          // 0..255
    const int c4 = threadIdx.x;         // 0..255

    __shared__ int   s_ax0[POOL];
    __shared__ int   s_ax1[POOL];
    __shared__ float s_fx [POOL];

    const int x1 = (int)rois[r * 4 + 0];
    const int y1 = (int)rois[r * 4 + 1];
    const int x2 = (int)rois[r * 4 + 2];
    const int y2 = (int)rois[r * 4 + 3];

    if (threadIdx.x < POOL) {
        const float ww = (float)(x2 - x1);
        const float src_x = (float)threadIdx.x * (ww * (1.0f / POOL));
        const int   x0 = (int)floorf(src_x);
        const int   x1i = min(x0 + 1, (x2 - x1) - 1);
        const float fx = src_x - (float)x0;
        const int   ax0 = min(max(x1 + x0, 0), W - 1);
        int         ax1 = min(max(x1 + x1i, 0), W - 1);
        if (fx == 0.0f) ax1 = ax0;      // zero-weight corner -> alias address
        s_fx [threadIdx.x] = fx;
        s_ax0[threadIdx.x] = ax0;
        s_ax1[threadIdx.x] = ax1;
    }

    const float hh = (float)(y2 - y1);
    const float src_y = (float)py * (hh * (1.0f / POOL));
    const int   y0 = (int)floorf(src_y);
    const float fy = src_y - (float)y0;
    const int   y1i = min(y0 + 1, (y2 - y1) - 1);
    const int   ay0 = min(max(y1 + y0, 0), H - 1);
    int         ay1 = min(max(y1 + y1i, 0), H - 1);
    if (fy == 0.0f) ay1 = ay0;          // zero-weight row -> alias address

    __syncthreads();

    const float4* __restrict__ row0 = img + (size_t)(ay0 * W) * C4 + c4;
    const float4* __restrict__ row1 = img + (size_t)(ay1 * W) * C4 + c4;
    float4* __restrict__ orow = out + ((size_t)(r * POOL + py) * POOL) * C4 + c4;

    #pragma unroll
    for (int px = 0; px < POOL; px++) {
        const int   ax0 = s_ax0[px];
        const int   ax1 = s_ax1[px];
        const float fx  = s_fx[px];

        const float4 v00 = row0[ax0 * C4];
        const float4 v01 = row0[ax1 * C4];
        const float4 v10 = row1[ax0 * C4];
        const float4 v11 = row1[ax1 * C4];

        float4 o;
        {
            float top = v00.x + (v01.x - v00.x) * fx;
            float bot = v10.x + (v11.x - v10.x) * fx;
            o.x = top + (bot - top) * fy;
        }
        {
            float top = v00.y + (v01.y - v00.y) * fx;
            float bot = v10.y + (v11.y - v10.y) * fx;
            o.y = top + (bot - top) * fy;
        }
        {
            float top = v00.z + (v01.z - v00.z) * fx;
            float bot = v10.z + (v11.z - v10.z) * fx;
            o.z = top + (bot - top) * fy;
        }
        {
            float top = v00.w + (v01.w - v00.w) * fx;
            float bot = v10.w + (v11.w - v10.w) * fx;
            o.w = top + (bot - top) * fy;
        }

        __stwt(&orow[(size_t)px * C4], o);   // write-through: bypass L2 fill
    }
}

extern "C" void kernel_launch(void* const* d_in, const int* in_sizes, int n_in,
                              void* d_out, int out_size) {
    const float4* img  = (const float4*)d_in[0];
    const float*  rois = (const float*)d_in[1];
    float4*       out  = (float4*)d_out;

    dim3 grid(POOL, R);
    roi_resize_kernel<<<grid, 256>>>(img, rois, out);
}

// round 9
// speedup vs baseline: 1.6028x; 1.0634x over previous
#include <cuda_runtime.h>

#define POOL 14
#define H 128
#define W 128
#define C 1024
#define R 256
#define C4 (C / 4)

// FINAL (R6 config, best measured 53.3us — ~4% above the DRAM write floor).
//
// One CTA per (roi, py) output row; 256 threads = one float4 channel-group
// each. x-side gather tuples precomputed by threads 0..13 into shared;
// y-side scalars once per CTA. Full 14-px unroll: ptxas front-batches the
// 4 straight LDG.128 per px (needs 48 regs — capping to 40 cost +68%).
// Streaming __stcs keeps the 64MB img L2-resident (writes are ~95% of DRAM
// traffic, ~4.0TB/s pure-write ceiling). Zero-weight corners (fx==0 /
// fy==0, ~26% each) are aliased to the already-loaded address in the
// precompute — bit-exact, converts those reads into L1 hits with zero
// inner-loop instruction cost.
//
// Measured dead ends: sw-pipelining, reg caps, per-px predicated skips,
// uniform two-path bodies, __stwt. Do not reintroduce.
__global__ __launch_bounds__(256) void roi_resize_kernel(
    const float4* __restrict__ img,   // [H, W, C4]
    const float*  __restrict__ rois,  // [R, 4]
    float4*       __restrict__ out)   // [R, POOL, POOL, C4]
{
    const int py = blockIdx.x;          // 0..13
    const int r  = blockIdx.y;          // 0..255
    const int c4 = threadIdx.x;         // 0..255

    __shared__ int   s_ax0[POOL];
    __shared__ int   s_ax1[POOL];
    __shared__ float s_fx [POOL];

    const int x1 = (int)rois[r * 4 + 0];
    const int y1 = (int)rois[r * 4 + 1];
    const int x2 = (int)rois[r * 4 + 2];
    const int y2 = (int)rois[r * 4 + 3];

    if (threadIdx.x < POOL) {
        const float ww = (float)(x2 - x1);
        const float src_x = (float)threadIdx.x * (ww * (1.0f / POOL));
        const int   x0 = (int)floorf(src_x);
        const int   x1i = min(x0 + 1, (x2 - x1) - 1);
        const float fx = src_x - (float)x0;
        const int   ax0 = min(max(x1 + x0, 0), W - 1);
        int         ax1 = min(max(x1 + x1i, 0), W - 1);
        if (fx == 0.0f) ax1 = ax0;      // zero-weight corner -> alias address
        s_fx [threadIdx.x] = fx;
        s_ax0[threadIdx.x] = ax0;
        s_ax1[threadIdx.x] = ax1;
    }

    const float hh = (float)(y2 - y1);
    const float src_y = (float)py * (hh * (1.0f / POOL));
    const int   y0 = (int)floorf(src_y);
    const float fy = src_y - (float)y0;
    const int   y1i = min(y0 + 1, (y2 - y1) - 1);
    const int   ay0 = min(max(y1 + y0, 0), H - 1);
    int         ay1 = min(max(y1 + y1i, 0), H - 1);
    if (fy == 0.0f) ay1 = ay0;          // zero-weight row -> alias address

    __syncthreads();

    const float4* __restrict__ row0 = img + (size_t)(ay0 * W) * C4 + c4;
    const float4* __restrict__ row1 = img + (size_t)(ay1 * W) * C4 + c4;
    float4* __restrict__ orow = out + ((size_t)(r * POOL + py) * POOL) * C4 + c4;

    #pragma unroll
    for (int px = 0; px < POOL; px++) {
        const int   ax0 = s_ax0[px];
        const int   ax1 = s_ax1[px];
        const float fx  = s_fx[px];

        const float4 v00 = row0[ax0 * C4];
        const float4 v01 = row0[ax1 * C4];
        const float4 v10 = row1[ax0 * C4];
        const float4 v11 = row1[ax1 * C4];

        float4 o;
        {
            float top = v00.x + (v01.x - v00.x) * fx;
            float bot = v10.x + (v11.x - v10.x) * fx;
            o.x = top + (bot - top) * fy;
        }
        {
            float top = v00.y + (v01.y - v00.y) * fx;
            float bot = v10.y + (v11.y - v10.y) * fx;
            o.y = top + (bot - top) * fy;
        }
        {
            float top = v00.z + (v01.z - v00.z) * fx;
            float bot = v10.z + (v11.z - v10.z) * fx;
            o.z = top + (bot - top) * fy;
        }
        {
            float top = v00.w + (v01.w - v00.w) * fx;
            float bot = v10.w + (v11.w - v10.w) * fx;
            o.w = top + (bot - top) * fy;
        }

        __stcs(&orow[(size_t)px * C4], o);   // evict-first streaming store
    }
}

extern "C" void kernel_launch(void* const* d_in, const int* in_sizes, int n_in,
                              void* d_out, int out_size) {
    const float4* img  = (const float4*)d_in[0];
    const float*  rois = (const float*)d_in[1];
    float4*       out  = (float4*)d_out;

    dim3 grid(POOL, R);
    roi_resize_kernel<<<grid, 256>>>(img, rois, out);
}